// round 8
// baseline (speedup 1.0000x reference)
#include <cuda_runtime.h>
#include <cuda_bf16.h>
#include <math.h>
#include <stdint.h>

// Problem constants: B=4, S=4096, D=512
#define BB 4
#define SS 4096
#define DD 512
#define MT (BB * SS)  // 16384

// GEMM tiling (all variants stage 128 rows x 128B per matrix per stage)
#define STAGES 3
#define STAGE_A 16384
#define STAGE_BYTES 32768
#define SMEM_MAIN (STAGES * STAGE_BYTES)   // 98304
#define SOUT_STRIDE 132
#define SMEM_TOTAL (SMEM_MAIN + 512)
#define NCH_TF32 16   // K=512 / 32 floats per 128B row-chunk
#define NCH_BF16 8    // K=512 / 64 bf16  per 128B row-chunk

// ---------------------------------------------------------------------------
// Scratch (__device__ globals; no allocation allowed)
// ---------------------------------------------------------------------------
__device__ float g_X[(size_t)MT * DD];               // tf32-rounded xs (P GEMM A)
__device__ __nv_bfloat16 g_Xb[(size_t)MT * DD];      // bf16 xs (K/Q proj A)
__device__ __nv_bfloat16 g_Wb[(size_t)2 * DD * DD];  // bf16 Wk | Wq
__device__ float g_Wl[(size_t)DD * DD];              // tf32 Wl
__device__ float g_WvT[(size_t)DD * DD];             // tf32 Wv^T
__device__ float g_Wc[(size_t)DD * DD];              // Wc = Wl@Wv (tf32), K-major
__device__ float g_bvl[DD];                          // Wl@bv
__device__ __nv_bfloat16 g_KQ[(size_t)2 * MT * DD];  // K | Q in bf16
__device__ float g_P[(size_t)MT * DD];               // P = X@Wc^T + bvl
__device__ __nv_bfloat16 g_E[(size_t)BB * SS * SS];  // exp(qk/512), bf16
__device__ float g_Z[MT];                            // col sums -> inverted in place
__device__ float g_rowsum[MT];

// ---------------------------------------------------------------------------
// PTX helpers — ISA-portable only (toolchain targets compute_103 WITHOUT 'a').
// ---------------------------------------------------------------------------
static __device__ __forceinline__ uint32_t smem_u32(const void* p) {
    uint32_t a;
    asm("{ .reg .u64 t; cvta.to.shared.u64 t, %1; cvt.u32.u64 %0, t; }"
        : "=r"(a) : "l"(p));
    return a;
}

#define CP_ASYNC16(sm, gp) \
    asm volatile("cp.async.cg.shared.global [%0], [%1], 16;" :: "r"(sm), "l"(gp) : "memory")
#define CP_COMMIT() asm volatile("cp.async.commit_group;" ::: "memory")
#define CP_WAIT(n)  asm volatile("cp.async.wait_group %0;" :: "n"(n) : "memory")

#define LDSM4(r0, r1, r2, r3, addr) \
    asm volatile("ldmatrix.sync.aligned.m8n8.x4.shared.b16 {%0,%1,%2,%3}, [%4];" \
                 : "=r"(r0), "=r"(r1), "=r"(r2), "=r"(r3) : "r"(addr))

#define MMA_TF32(c, a, b) \
    asm volatile("mma.sync.aligned.m16n8k8.row.col.f32.tf32.tf32.f32 " \
                 "{%0,%1,%2,%3},{%4,%5,%6,%7},{%8,%9},{%0,%1,%2,%3};" \
                 : "+f"((c)[0]), "+f"((c)[1]), "+f"((c)[2]), "+f"((c)[3]) \
                 : "r"((a)[0]), "r"((a)[1]), "r"((a)[2]), "r"((a)[3]), \
                   "r"((b)[0]), "r"((b)[1]))

#define MMA_BF16(c, a, b) \
    asm volatile("mma.sync.aligned.m16n8k16.row.col.f32.bf16.bf16.f32 " \
                 "{%0,%1,%2,%3},{%4,%5,%6,%7},{%8,%9},{%0,%1,%2,%3};" \
                 : "+f"((c)[0]), "+f"((c)[1]), "+f"((c)[2]), "+f"((c)[3]) \
                 : "r"((a)[0]), "r"((a)[1]), "r"((a)[2]), "r"((a)[3]), \
                   "r"((b)[0]), "r"((b)[1]))

static __device__ __forceinline__ float round_tf32(float x) {
    uint32_t u;
    asm("cvt.rna.tf32.f32 %0, %1;" : "=r"(u) : "f"(x));
    return __uint_as_float(u);
}

// ---------------------------------------------------------------------------
// Shared fragment-addressing (identical byte math for tf32-k8 and bf16-k16).
// ---------------------------------------------------------------------------
struct FragAddr {
    uint32_t so[4];
    uint32_t aOff[4], bOff[2];
    uint32_t swx, cAsel, cBsel;
};

static __device__ __forceinline__ FragAddr make_addr(int tid) {
    FragAddr F;
    const int lane = tid & 31, wid = tid >> 5;
    const int wm = wid & 1, wn = wid >> 1;
#pragma unroll
    for (int i = 0; i < 4; i++) {
        int g = tid + 256 * i;
        int row = g >> 3, cb = (g & 7) * 16;
        uint32_t raw = (uint32_t)row * 128u + (uint32_t)cb;
        F.so[i] = raw ^ ((raw >> 3) & 0x70u);
    }
    const int arow = ((lane >> 3) & 1) * 8 + (lane & 7);
    const int brow = ((lane >> 4) & 1) * 8 + (lane & 7);
#pragma unroll
    for (int f = 0; f < 4; f++) F.aOff[f] = (uint32_t)((wm * 64 + f * 16 + arow) * 128);
#pragma unroll
    for (int j = 0; j < 2; j++) F.bOff[j] = (uint32_t)((wn * 32 + j * 16 + brow) * 128);
    F.swx = ((uint32_t)(lane & 7)) << 4;
    F.cAsel = (uint32_t)(((lane >> 4) & 1) * 16);
    F.cBsel = (uint32_t)(((lane >> 3) & 1) * 16);
    return F;
}

template <int BF16>
static __device__ __forceinline__ void compute_stage(
    const FragAddr& F, uint32_t stA, uint32_t stB, float acc[4][4][4])
{
#pragma unroll
    for (int ks = 0; ks < 4; ks++) {
        uint32_t a[4][4], b[2][4];
        uint32_t cA = (uint32_t)ks * 32u + F.cAsel;
        uint32_t cB = (uint32_t)ks * 32u + F.cBsel;
#pragma unroll
        for (int f = 0; f < 4; f++)
            LDSM4(a[f][0], a[f][1], a[f][2], a[f][3],
                  stA + F.aOff[f] + (cA ^ F.swx));
#pragma unroll
        for (int j = 0; j < 2; j++)
            LDSM4(b[j][0], b[j][1], b[j][2], b[j][3],
                  stB + F.bOff[j] + (cB ^ F.swx));
#pragma unroll
        for (int f = 0; f < 4; f++)
#pragma unroll
            for (int nf = 0; nf < 4; nf++) {
                if (BF16) MMA_BF16(acc[f][nf], a[f], &b[nf >> 1][(nf & 1) * 2]);
                else      MMA_TF32(acc[f][nf], a[f], &b[nf >> 1][(nf & 1) * 2]);
            }
    }
}

static __device__ __forceinline__ void acc_to_smem(
    float* sOut, int lane, int wid, float acc[4][4][4])
{
    const int wm = wid & 1, wn = wid >> 1;
#pragma unroll
    for (int f = 0; f < 4; f++) {
        int row = wm * 64 + f * 16 + (lane >> 2);
#pragma unroll
        for (int nf = 0; nf < 4; nf++) {
            int col = wn * 32 + nf * 8 + 2 * (lane & 3);
            *(float2*)&sOut[row * SOUT_STRIDE + col] =
                make_float2(acc[f][nf][0], acc[f][nf][1]);
            *(float2*)&sOut[(row + 8) * SOUT_STRIDE + col] =
                make_float2(acc[f][nf][2], acc[f][nf][3]);
        }
    }
}

// ---------------------------------------------------------------------------
// tf32 GEMM. MODE 0: C = round_tf32(acc), no bias  (Wc = Wl@Wv)
//           MODE 1: C = acc + bias[n], fp32        (P = X@Wc^T + bvl)
// ---------------------------------------------------------------------------
template <int MODE>
__global__ __launch_bounds__(256) void gemm_tf32(
    const float* __restrict__ Ag, const float* __restrict__ Bg,
    const float* __restrict__ bias, float* __restrict__ Cout)
{
    extern __shared__ char smem[];
    const uint32_t sbase = smem_u32(smem);
    float* sOut = (float*)smem;
    const int tid = threadIdx.x;
    const int lane = tid & 31, wid = tid >> 5;
    const int m0 = blockIdx.y * 128, n0 = blockIdx.x * 128;

    const char* Ab = (const char*)Ag;
    const char* Bb = (const char*)Bg;

    FragAddr F = make_addr(tid);
    uint32_t gA[4], gB[4];
#pragma unroll
    for (int i = 0; i < 4; i++) {
        int g = tid + 256 * i;
        int row = g >> 3, cb = (g & 7) * 16;
        gA[i] = (uint32_t)((m0 + row) * DD) * 4u + (uint32_t)cb;
        gB[i] = (uint32_t)((n0 + row) * DD) * 4u + (uint32_t)cb;
    }

    float acc[4][4][4];
#pragma unroll
    for (int f = 0; f < 4; f++)
#pragma unroll
        for (int nf = 0; nf < 4; nf++)
#pragma unroll
            for (int r = 0; r < 4; r++) acc[f][nf][r] = 0.f;

    auto load_chunk = [&](int c, int s) {
        uint32_t stA = sbase + (uint32_t)s * STAGE_BYTES;
        uint32_t stB = stA + STAGE_A;
        uint32_t ko = (uint32_t)c * 128u;
#pragma unroll
        for (int i = 0; i < 4; i++) {
            CP_ASYNC16(stA + F.so[i], Ab + gA[i] + ko);
            CP_ASYNC16(stB + F.so[i], Bb + gB[i] + ko);
        }
    };

    load_chunk(0, 0); CP_COMMIT();
    load_chunk(1, 1); CP_COMMIT();
    for (int c = 0; c < NCH_TF32; c++) {
        CP_WAIT(1);
        __syncthreads();
        if (c + 2 < NCH_TF32) load_chunk(c + 2, (c + 2) % 3);
        CP_COMMIT();
        uint32_t stA = sbase + (uint32_t)(c % 3) * STAGE_BYTES;
        compute_stage<0>(F, stA, stA + STAGE_A, acc);
    }
    __syncthreads();
    acc_to_smem(sOut, lane, wid, acc);
    __syncthreads();

    const int col = (tid & 31) * 4;
    float4 bv = make_float4(0.f, 0.f, 0.f, 0.f);
    if (MODE == 1) bv = *(const float4*)&bias[n0 + col];
#pragma unroll
    for (int i = 0; i < 16; i++) {
        int row = (tid >> 5) + i * 8;
        float4 v = *(float4*)&sOut[row * SOUT_STRIDE + col];
        if (MODE == 0) {
            v.x = round_tf32(v.x); v.y = round_tf32(v.y);
            v.z = round_tf32(v.z); v.w = round_tf32(v.w);
        } else {
            v.x += bv.x; v.y += bv.y; v.z += bv.z; v.w += bv.w;
        }
        *(float4*)&Cout[(size_t)(m0 + row) * DD + n0 + col] = v;
    }
}

// ---------------------------------------------------------------------------
// bf16 K/Q projection: KQ[z] = bf16(Xb @ Wb[z]^T + bias_z), z=0(K),1(Q)
// ---------------------------------------------------------------------------
__global__ __launch_bounds__(256) void gemm_kq_bf16(
    const float* __restrict__ bk_, const float* __restrict__ bq_)
{
    extern __shared__ char smem[];
    const uint32_t sbase = smem_u32(smem);
    float* sOut = (float*)smem;
    const int tid = threadIdx.x;
    const int lane = tid & 31, wid = tid >> 5;
    const int m0 = blockIdx.y * 128, n0 = blockIdx.x * 128;
    const int z = blockIdx.z;

    const char* Ab = (const char*)g_Xb;
    const char* Bb = (const char*)(g_Wb + (size_t)z * DD * DD);
    const float* bias = z ? bq_ : bk_;

    FragAddr F = make_addr(tid);
    uint32_t gA[4], gB[4];
#pragma unroll
    for (int i = 0; i < 4; i++) {
        int g = tid + 256 * i;
        int row = g >> 3, cb = (g & 7) * 16;
        gA[i] = (uint32_t)((m0 + row) * DD) * 2u + (uint32_t)cb;
        gB[i] = (uint32_t)((n0 + row) * DD) * 2u + (uint32_t)cb;
    }

    float acc[4][4][4];
#pragma unroll
    for (int f = 0; f < 4; f++)
#pragma unroll
        for (int nf = 0; nf < 4; nf++)
#pragma unroll
            for (int r = 0; r < 4; r++) acc[f][nf][r] = 0.f;

    auto load_chunk = [&](int c, int s) {
        uint32_t stA = sbase + (uint32_t)s * STAGE_BYTES;
        uint32_t stB = stA + STAGE_A;
        uint32_t ko = (uint32_t)c * 128u;
#pragma unroll
        for (int i = 0; i < 4; i++) {
            CP_ASYNC16(stA + F.so[i], Ab + gA[i] + ko);
            CP_ASYNC16(stB + F.so[i], Bb + gB[i] + ko);
        }
    };

    load_chunk(0, 0); CP_COMMIT();
    load_chunk(1, 1); CP_COMMIT();
    for (int c = 0; c < NCH_BF16; c++) {
        CP_WAIT(1);
        __syncthreads();
        if (c + 2 < NCH_BF16) load_chunk(c + 2, (c + 2) % 3);
        CP_COMMIT();
        uint32_t stA = sbase + (uint32_t)(c % 3) * STAGE_BYTES;
        compute_stage<1>(F, stA, stA + STAGE_A, acc);
    }
    __syncthreads();
    acc_to_smem(sOut, lane, wid, acc);
    __syncthreads();

    const int col = (tid & 31) * 4;
    float4 bv = *(const float4*)&bias[n0 + col];
    __nv_bfloat16* Cb = g_KQ + (size_t)z * MT * DD;
#pragma unroll
    for (int i = 0; i < 16; i++) {
        int row = (tid >> 5) + i * 8;
        float4 v = *(float4*)&sOut[row * SOUT_STRIDE + col];
        v.x += bv.x; v.y += bv.y; v.z += bv.z; v.w += bv.w;
        __nv_bfloat162 p0 = __floats2bfloat162_rn(v.x, v.y);
        __nv_bfloat162 p1 = __floats2bfloat162_rn(v.z, v.w);
        uint2 pk = make_uint2(*(uint32_t*)&p0, *(uint32_t*)&p1);
        *(uint2*)&Cb[(size_t)(m0 + row) * DD + n0 + col] = pk;
    }
}

// ---------------------------------------------------------------------------
// bf16 qk GEMM: E[b] = bf16(exp((K_b @ Q_b^T)/512)), column sums into g_Z.
// ---------------------------------------------------------------------------
__global__ __launch_bounds__(256) void gemm_qk_bf16()
{
    extern __shared__ char smem[];
    const uint32_t sbase = smem_u32(smem);
    float* sOut = (float*)smem;
    float* sZ   = (float*)(smem + SMEM_MAIN);
    const int tid = threadIdx.x;
    const int lane = tid & 31, wid = tid >> 5;
    const int m0 = blockIdx.y * 128, n0 = blockIdx.x * 128;
    const int z = blockIdx.z;

    const char* Ab = (const char*)(g_KQ + (size_t)z * SS * DD);
    const char* Bb = (const char*)(g_KQ + (size_t)MT * DD + (size_t)z * SS * DD);

    if (tid < 128) sZ[tid] = 0.f;

    FragAddr F = make_addr(tid);
    uint32_t gA[4], gB[4];
#pragma unroll
    for (int i = 0; i < 4; i++) {
        int g = tid + 256 * i;
        int row = g >> 3, cb = (g & 7) * 16;
        gA[i] = (uint32_t)((m0 + row) * DD) * 2u + (uint32_t)cb;
        gB[i] = (uint32_t)((n0 + row) * DD) * 2u + (uint32_t)cb;
    }

    float acc[4][4][4];
#pragma unroll
    for (int f = 0; f < 4; f++)
#pragma unroll
        for (int nf = 0; nf < 4; nf++)
#pragma unroll
            for (int r = 0; r < 4; r++) acc[f][nf][r] = 0.f;

    auto load_chunk = [&](int c, int s) {
        uint32_t stA = sbase + (uint32_t)s * STAGE_BYTES;
        uint32_t stB = stA + STAGE_A;
        uint32_t ko = (uint32_t)c * 128u;
#pragma unroll
        for (int i = 0; i < 4; i++) {
            CP_ASYNC16(stA + F.so[i], Ab + gA[i] + ko);
            CP_ASYNC16(stB + F.so[i], Bb + gB[i] + ko);
        }
    };

    load_chunk(0, 0); CP_COMMIT();
    load_chunk(1, 1); CP_COMMIT();
    for (int c = 0; c < NCH_BF16; c++) {
        CP_WAIT(1);
        __syncthreads();
        if (c + 2 < NCH_BF16) load_chunk(c + 2, (c + 2) % 3);
        CP_COMMIT();
        uint32_t stA = sbase + (uint32_t)(c % 3) * STAGE_BYTES;
        compute_stage<1>(F, stA, stA + STAGE_A, acc);
    }
    __syncthreads();
    acc_to_smem(sOut, lane, wid, acc);
    __syncthreads();

    const int col = (tid & 31) * 4;
    float csum0 = 0.f, csum1 = 0.f, csum2 = 0.f, csum3 = 0.f;
    const float inv512 = 0.001953125f;
    __nv_bfloat16* Cb = g_E + (size_t)z * SS * SS;
#pragma unroll
    for (int i = 0; i < 16; i++) {
        int row = (tid >> 5) + i * 8;
        float4 v = *(float4*)&sOut[row * SOUT_STRIDE + col];
        v.x = __expf(v.x * inv512); v.y = __expf(v.y * inv512);
        v.z = __expf(v.z * inv512); v.w = __expf(v.w * inv512);
        csum0 += v.x; csum1 += v.y; csum2 += v.z; csum3 += v.w;
        __nv_bfloat162 p0 = __floats2bfloat162_rn(v.x, v.y);
        __nv_bfloat162 p1 = __floats2bfloat162_rn(v.z, v.w);
        uint2 pk = make_uint2(*(uint32_t*)&p0, *(uint32_t*)&p1);
        *(uint2*)&Cb[(size_t)(m0 + row) * SS + n0 + col] = pk;
    }
    atomicAdd(&sZ[col + 0], csum0);
    atomicAdd(&sZ[col + 1], csum1);
    atomicAdd(&sZ[col + 2], csum2);
    atomicAdd(&sZ[col + 3], csum3);
    __syncthreads();
    if (tid < 128)
        atomicAdd(&g_Z[(size_t)z * SS + n0 + tid], sZ[tid]);
}

// ---------------------------------------------------------------------------
// Prep / small kernels
// ---------------------------------------------------------------------------
// y=0: xs -> g_X (tf32) + g_Xb (bf16);  y=1: Wk -> g_Wb[0];  y=2: Wq -> g_Wb[1];
// y=3: Wl -> g_Wl (tf32)
__global__ __launch_bounds__(256) void prep_kernel(
    const float* __restrict__ xs, const float* __restrict__ Wk,
    const float* __restrict__ Wq, const float* __restrict__ Wl)
{
    const int t = blockIdx.x * 256 + threadIdx.x;
    const int which = blockIdx.y;
    if (which == 0) {
        if (t < MT * DD / 4) {
            float4 v = ((const float4*)xs)[t];
            float4 r;
            r.x = round_tf32(v.x); r.y = round_tf32(v.y);
            r.z = round_tf32(v.z); r.w = round_tf32(v.w);
            ((float4*)g_X)[t] = r;
            __nv_bfloat162 p0 = __floats2bfloat162_rn(v.x, v.y);
            __nv_bfloat162 p1 = __floats2bfloat162_rn(v.z, v.w);
            ((uint2*)g_Xb)[t] = make_uint2(*(uint32_t*)&p0, *(uint32_t*)&p1);
        }
    } else if (which <= 2) {
        if (t < DD * DD / 4) {
            const float4* src = (const float4*)(which == 1 ? Wk : Wq);
            float4 v = src[t];
            __nv_bfloat162 p0 = __floats2bfloat162_rn(v.x, v.y);
            __nv_bfloat162 p1 = __floats2bfloat162_rn(v.z, v.w);
            ((uint2*)(g_Wb + (size_t)(which - 1) * DD * DD))[t] =
                make_uint2(*(uint32_t*)&p0, *(uint32_t*)&p1);
        }
    } else {
        if (t < DD * DD / 4) {
            float4 v = ((const float4*)Wl)[t];
            v.x = round_tf32(v.x); v.y = round_tf32(v.y);
            v.z = round_tf32(v.z); v.w = round_tf32(v.w);
            ((float4*)g_Wl)[t] = v;
        }
    }
}

// g_WvT[k,j] = round_tf32(Wv[j,k])
__global__ __launch_bounds__(256) void transWv_kernel(const float* __restrict__ Wv)
{
    __shared__ float tbuf[32][33];
    const int bx = blockIdx.x * 32, by = blockIdx.y * 32;
    const int tx = threadIdx.x & 31, ty = threadIdx.x >> 5;  // 32x8
#pragma unroll
    for (int i = 0; i < 32; i += 8)
        tbuf[ty + i][tx] = Wv[(size_t)(by + ty + i) * DD + bx + tx];
    __syncthreads();
#pragma unroll
    for (int i = 0; i < 32; i += 8)
        g_WvT[(size_t)(bx + ty + i) * DD + by + tx] = round_tf32(tbuf[tx][ty + i]);
}

// g_bvl[n] = sum_j Wl[n,j] * bv[j]
__global__ __launch_bounds__(256) void bvl_kernel(
    const float* __restrict__ Wl, const float* __restrict__ bv)
{
    const int n = blockIdx.x * 8 + (threadIdx.x >> 5);
    const int lane = threadIdx.x & 31;
    const float* row = Wl + (size_t)n * DD;
    float s = 0.f;
#pragma unroll
    for (int i = 0; i < DD / 32; i++) s += row[lane + i * 32] * bv[lane + i * 32];
#pragma unroll
    for (int o = 16; o > 0; o >>= 1) s += __shfl_xor_sync(0xffffffffu, s, o);
    if (lane == 0) g_bvl[n] = s;
}

__global__ void zeroZ_kernel() {
    int i = blockIdx.x * 256 + threadIdx.x;
    if (i < MT) g_Z[i] = 0.f;
}
__global__ void invZ_kernel() {
    int i = blockIdx.x * 256 + threadIdx.x;
    if (i < MT) g_Z[i] = 1.0f / g_Z[i];
}

// rowsum[m] = sum_e E[m,e]*invZ[b,e]  (E bf16)
__global__ __launch_bounds__(256) void rowsum_kernel()
{
    const int m = blockIdx.x;
    const int b = m >> 12;
    const __nv_bfloat16* __restrict__ Er = g_E + (size_t)m * SS;
    const float* __restrict__ iz = g_Z + b * SS;
    float s = 0.f;
#pragma unroll
    for (int it = 0; it < 2; it++) {
        int e = (threadIdx.x + it * 256) * 8;
        uint4 raw = *(const uint4*)(Er + e);
        float4 z0 = *(const float4*)(iz + e);
        float4 z1 = *(const float4*)(iz + e + 4);
        float2 p0 = __bfloat1622float2(*(__nv_bfloat162*)&raw.x);
        float2 p1 = __bfloat1622float2(*(__nv_bfloat162*)&raw.y);
        float2 p2 = __bfloat1622float2(*(__nv_bfloat162*)&raw.z);
        float2 p3 = __bfloat1622float2(*(__nv_bfloat162*)&raw.w);
        s += p0.x * z0.x + p0.y * z0.y + p1.x * z0.z + p1.y * z0.w
           + p2.x * z1.x + p2.y * z1.y + p3.x * z1.z + p3.y * z1.w;
    }
#pragma unroll
    for (int o = 16; o > 0; o >>= 1) s += __shfl_xor_sync(0xffffffffu, s, o);
    __shared__ float red[8];
    if ((threadIdx.x & 31) == 0) red[threadIdx.x >> 5] = s;
    __syncthreads();
    if (threadIdx.x == 0) {
        float t = 0.f;
#pragma unroll
        for (int w = 0; w < 8; w++) t += red[w];
        g_rowsum[m] = t;
    }
}

// out[m,:] = tanh(rowsum[m] * P[m,:] + bl)
__global__ __launch_bounds__(128) void final_kernel(
    const float* __restrict__ bl, float* __restrict__ out)
{
    const int m = blockIdx.x;
    const float r = g_rowsum[m];
    float4 p = ((const float4*)(g_P + (size_t)m * DD))[threadIdx.x];
    float4 b = ((const float4*)bl)[threadIdx.x];
    p.x = tanhf(fmaf(r, p.x, b.x)); p.y = tanhf(fmaf(r, p.y, b.y));
    p.z = tanhf(fmaf(r, p.z, b.z)); p.w = tanhf(fmaf(r, p.w, b.w));
    ((float4*)(out + (size_t)m * DD))[threadIdx.x] = p;
}

// ---------------------------------------------------------------------------
extern "C" void kernel_launch(void* const* d_in, const int* in_sizes, int n_in,
                              void* d_out, int out_size)
{
    const float* xs = (const float*)d_in[0];
    const float* Wk = (const float*)d_in[1];
    const float* bk = (const float*)d_in[2];
    const float* Wq = (const float*)d_in[3];
    const float* bq = (const float*)d_in[4];
    const float* Wv = (const float*)d_in[5];
    const float* bv = (const float*)d_in[6];
    const float* Wl = (const float*)d_in[7];
    const float* bl = (const float*)d_in[8];
    float* out = (float*)d_out;
    (void)in_sizes; (void)n_in; (void)out_size;

    float *pX, *pWl, *pWvT, *pWc, *pBvl, *pP;
    cudaGetSymbolAddress((void**)&pX, g_X);
    cudaGetSymbolAddress((void**)&pWl, g_Wl);
    cudaGetSymbolAddress((void**)&pWvT, g_WvT);
    cudaGetSymbolAddress((void**)&pWc, g_Wc);
    cudaGetSymbolAddress((void**)&pBvl, g_bvl);
    cudaGetSymbolAddress((void**)&pP, g_P);

    cudaFuncSetAttribute(gemm_tf32<0>, cudaFuncAttributeMaxDynamicSharedMemorySize, SMEM_TOTAL);
    cudaFuncSetAttribute(gemm_tf32<1>, cudaFuncAttributeMaxDynamicSharedMemorySize, SMEM_TOTAL);
    cudaFuncSetAttribute(gemm_kq_bf16, cudaFuncAttributeMaxDynamicSharedMemorySize, SMEM_TOTAL);
    cudaFuncSetAttribute(gemm_qk_bf16, cudaFuncAttributeMaxDynamicSharedMemorySize, SMEM_TOTAL);

    zeroZ_kernel<<<MT / 256, 256>>>();
    prep_kernel<<<dim3(MT * DD / 1024, 4), 256>>>(xs, Wk, Wq, Wl);
    transWv_kernel<<<dim3(16, 16), 256>>>(Wv);
    bvl_kernel<<<DD / 8, 256>>>(Wl, bv);
    // Wc = Wl @ Wv  (C[n,k] = sum_j Wl[n,j] * WvT[k,j])
    gemm_tf32<0><<<dim3(4, 4), 256, SMEM_TOTAL>>>(pWl, pWvT, nullptr, pWc);
    // K/Q projections in bf16
    gemm_kq_bf16<<<dim3(4, 128, 2), 256, SMEM_TOTAL>>>(bk, bq);
    // qk
    gemm_qk_bf16<<<dim3(32, 32, BB), 256, SMEM_TOTAL>>>();
    // P = X @ Wc^T + bvl
    gemm_tf32<1><<<dim3(4, 128), 256, SMEM_TOTAL>>>(pX, pWc, pBvl, pP);
    invZ_kernel<<<MT / 256, 256>>>();
    rowsum_kernel<<<MT, 256>>>();
    final_kernel<<<MT, 128>>>(bl, out);
}

// round 9
// speedup vs baseline: 1.4224x; 1.4224x over previous
#include <cuda_runtime.h>
#include <cuda_bf16.h>
#include <math.h>
#include <stdint.h>

// Problem constants: B=4, S=4096, D=512
#define BB 4
#define SS 4096
#define DD 512
#define MT (BB * SS)  // 16384

// GEMM tiling (all variants stage 128 rows x 128B per matrix per stage)
#define STAGES 3
#define STAGE_A 16384
#define STAGE_BYTES 32768
#define SMEM_MAIN (STAGES * STAGE_BYTES)   // 98304
#define SOUT_STRIDE 132
#define SMEM_TOTAL (SMEM_MAIN + 512)
#define NCH_TF32 16   // K=512 / 32 floats per 128B row-chunk
#define NCH_BF16 8    // K=512 / 64 bf16  per 128B row-chunk

// ---------------------------------------------------------------------------
// Scratch (__device__ globals; no allocation allowed)
// ---------------------------------------------------------------------------
__device__ float g_X[(size_t)MT * DD];               // tf32-rounded xs (V proj A)
__device__ __nv_bfloat16 g_Xb[(size_t)MT * DD];      // bf16 xs (K/Q proj A)
__device__ __nv_bfloat16 g_Wb[(size_t)2 * DD * DD];  // bf16 Wk | Wq
__device__ float g_Wv[(size_t)DD * DD];              // tf32 Wv
__device__ float g_Wl[(size_t)DD * DD];              // tf32 Wl
__device__ __nv_bfloat16 g_KQ[(size_t)2 * MT * DD];  // K | Q in bf16
__device__ float g_V[(size_t)MT * DD];               // V (tf32-rounded)
__device__ __nv_bfloat16 g_E[(size_t)BB * SS * SS];  // exp(qk/512), bf16
__device__ float g_Z[MT];                            // col sums -> inverted in place
__device__ float g_rowsum[MT];

// ---------------------------------------------------------------------------
// PTX helpers — ISA-portable only (toolchain targets compute_103 WITHOUT 'a').
// ---------------------------------------------------------------------------
static __device__ __forceinline__ uint32_t smem_u32(const void* p) {
    uint32_t a;
    asm("{ .reg .u64 t; cvta.to.shared.u64 t, %1; cvt.u32.u64 %0, t; }"
        : "=r"(a) : "l"(p));
    return a;
}

#define CP_ASYNC16(sm, gp) \
    asm volatile("cp.async.cg.shared.global [%0], [%1], 16;" :: "r"(sm), "l"(gp) : "memory")
#define CP_COMMIT() asm volatile("cp.async.commit_group;" ::: "memory")
#define CP_WAIT(n)  asm volatile("cp.async.wait_group %0;" :: "n"(n) : "memory")

#define LDSM4(r0, r1, r2, r3, addr) \
    asm volatile("ldmatrix.sync.aligned.m8n8.x4.shared.b16 {%0,%1,%2,%3}, [%4];" \
                 : "=r"(r0), "=r"(r1), "=r"(r2), "=r"(r3) : "r"(addr))

#define MMA_TF32(c, a, b) \
    asm volatile("mma.sync.aligned.m16n8k8.row.col.f32.tf32.tf32.f32 " \
                 "{%0,%1,%2,%3},{%4,%5,%6,%7},{%8,%9},{%0,%1,%2,%3};" \
                 : "+f"((c)[0]), "+f"((c)[1]), "+f"((c)[2]), "+f"((c)[3]) \
                 : "r"((a)[0]), "r"((a)[1]), "r"((a)[2]), "r"((a)[3]), \
                   "r"((b)[0]), "r"((b)[1]))

#define MMA_BF16(c, a, b) \
    asm volatile("mma.sync.aligned.m16n8k16.row.col.f32.bf16.bf16.f32 " \
                 "{%0,%1,%2,%3},{%4,%5,%6,%7},{%8,%9},{%0,%1,%2,%3};" \
                 : "+f"((c)[0]), "+f"((c)[1]), "+f"((c)[2]), "+f"((c)[3]) \
                 : "r"((a)[0]), "r"((a)[1]), "r"((a)[2]), "r"((a)[3]), \
                   "r"((b)[0]), "r"((b)[1]))

static __device__ __forceinline__ float round_tf32(float x) {
    uint32_t u;
    asm("cvt.rna.tf32.f32 %0, %1;" : "=r"(u) : "f"(x));
    return __uint_as_float(u);
}

// ---------------------------------------------------------------------------
// Shared fragment-addressing (identical byte math for tf32-k8 and bf16-k16).
// ---------------------------------------------------------------------------
struct FragAddr {
    uint32_t so[4];
    uint32_t aOff[4], bOff[2];
    uint32_t swx, cAsel, cBsel;
};

static __device__ __forceinline__ FragAddr make_addr(int tid) {
    FragAddr F;
    const int lane = tid & 31, wid = tid >> 5;
    const int wm = wid & 1, wn = wid >> 1;
#pragma unroll
    for (int i = 0; i < 4; i++) {
        int g = tid + 256 * i;
        int row = g >> 3, cb = (g & 7) * 16;
        uint32_t raw = (uint32_t)row * 128u + (uint32_t)cb;
        F.so[i] = raw ^ ((raw >> 3) & 0x70u);
    }
    const int arow = ((lane >> 3) & 1) * 8 + (lane & 7);
    const int brow = ((lane >> 4) & 1) * 8 + (lane & 7);
#pragma unroll
    for (int f = 0; f < 4; f++) F.aOff[f] = (uint32_t)((wm * 64 + f * 16 + arow) * 128);
#pragma unroll
    for (int j = 0; j < 2; j++) F.bOff[j] = (uint32_t)((wn * 32 + j * 16 + brow) * 128);
    F.swx = ((uint32_t)(lane & 7)) << 4;
    F.cAsel = (uint32_t)(((lane >> 4) & 1) * 16);
    F.cBsel = (uint32_t)(((lane >> 3) & 1) * 16);
    return F;
}

template <int BF16>
static __device__ __forceinline__ void compute_stage(
    const FragAddr& F, uint32_t stA, uint32_t stB, float acc[4][4][4])
{
#pragma unroll
    for (int ks = 0; ks < 4; ks++) {
        uint32_t a[4][4], b[2][4];
        uint32_t cA = (uint32_t)ks * 32u + F.cAsel;
        uint32_t cB = (uint32_t)ks * 32u + F.cBsel;
#pragma unroll
        for (int f = 0; f < 4; f++)
            LDSM4(a[f][0], a[f][1], a[f][2], a[f][3],
                  stA + F.aOff[f] + (cA ^ F.swx));
#pragma unroll
        for (int j = 0; j < 2; j++)
            LDSM4(b[j][0], b[j][1], b[j][2], b[j][3],
                  stB + F.bOff[j] + (cB ^ F.swx));
#pragma unroll
        for (int f = 0; f < 4; f++)
#pragma unroll
            for (int nf = 0; nf < 4; nf++) {
                if (BF16) MMA_BF16(acc[f][nf], a[f], &b[nf >> 1][(nf & 1) * 2]);
                else      MMA_TF32(acc[f][nf], a[f], &b[nf >> 1][(nf & 1) * 2]);
            }
    }
}

static __device__ __forceinline__ void acc_to_smem(
    float* sOut, int lane, int wid, float acc[4][4][4])
{
    const int wm = wid & 1, wn = wid >> 1;
#pragma unroll
    for (int f = 0; f < 4; f++) {
        int row = wm * 64 + f * 16 + (lane >> 2);
#pragma unroll
        for (int nf = 0; nf < 4; nf++) {
            int col = wn * 32 + nf * 8 + 2 * (lane & 3);
            *(float2*)&sOut[row * SOUT_STRIDE + col] =
                make_float2(acc[f][nf][0], acc[f][nf][1]);
            *(float2*)&sOut[(row + 8) * SOUT_STRIDE + col] =
                make_float2(acc[f][nf][2], acc[f][nf][3]);
        }
    }
}

// ---------------------------------------------------------------------------
// tf32 GEMM over fp32 operands (A row-major K-major, B K-major), K=512.
// MODE 0: g_V = round_tf32(acc + bias)   (V projection: A=g_X, B=g_Wv)
// MODE 2: out = tanh(acc + bias)         (final: A=scaled g_V, B=g_Wl)
// ---------------------------------------------------------------------------
template <int MODE>
__global__ __launch_bounds__(256) void gemm_tf32(
    const float* __restrict__ Ag, const float* __restrict__ Bg,
    const float* __restrict__ bias, float* __restrict__ Cout)
{
    extern __shared__ char smem[];
    const uint32_t sbase = smem_u32(smem);
    float* sOut = (float*)smem;
    const int tid = threadIdx.x;
    const int lane = tid & 31, wid = tid >> 5;
    const int m0 = blockIdx.y * 128, n0 = blockIdx.x * 128;

    const char* Ab = (const char*)Ag;
    const char* Bb = (const char*)Bg;

    FragAddr F = make_addr(tid);
    uint32_t gA[4], gB[4];
#pragma unroll
    for (int i = 0; i < 4; i++) {
        int g = tid + 256 * i;
        int row = g >> 3, cb = (g & 7) * 16;
        gA[i] = (uint32_t)((m0 + row) * DD) * 4u + (uint32_t)cb;
        gB[i] = (uint32_t)((n0 + row) * DD) * 4u + (uint32_t)cb;
    }

    float acc[4][4][4];
#pragma unroll
    for (int f = 0; f < 4; f++)
#pragma unroll
        for (int nf = 0; nf < 4; nf++)
#pragma unroll
            for (int r = 0; r < 4; r++) acc[f][nf][r] = 0.f;

    auto load_chunk = [&](int c, int s) {
        uint32_t stA = sbase + (uint32_t)s * STAGE_BYTES;
        uint32_t stB = stA + STAGE_A;
        uint32_t ko = (uint32_t)c * 128u;
#pragma unroll
        for (int i = 0; i < 4; i++) {
            CP_ASYNC16(stA + F.so[i], Ab + gA[i] + ko);
            CP_ASYNC16(stB + F.so[i], Bb + gB[i] + ko);
        }
    };

    load_chunk(0, 0); CP_COMMIT();
    load_chunk(1, 1); CP_COMMIT();
    for (int c = 0; c < NCH_TF32; c++) {
        CP_WAIT(1);
        __syncthreads();
        if (c + 2 < NCH_TF32) load_chunk(c + 2, (c + 2) % 3);
        CP_COMMIT();
        uint32_t stA = sbase + (uint32_t)(c % 3) * STAGE_BYTES;
        compute_stage<0>(F, stA, stA + STAGE_A, acc);
    }
    __syncthreads();
    acc_to_smem(sOut, lane, wid, acc);
    __syncthreads();

    const int col = (tid & 31) * 4;
    float4 bv = *(const float4*)&bias[n0 + col];
#pragma unroll
    for (int i = 0; i < 16; i++) {
        int row = (tid >> 5) + i * 8;
        float4 v = *(float4*)&sOut[row * SOUT_STRIDE + col];
        v.x += bv.x; v.y += bv.y; v.z += bv.z; v.w += bv.w;
        if (MODE == 0) {
            v.x = round_tf32(v.x); v.y = round_tf32(v.y);
            v.z = round_tf32(v.z); v.w = round_tf32(v.w);
        } else {
            v.x = tanhf(v.x); v.y = tanhf(v.y);
            v.z = tanhf(v.z); v.w = tanhf(v.w);
        }
        *(float4*)&Cout[(size_t)(m0 + row) * DD + n0 + col] = v;
    }
}

// ---------------------------------------------------------------------------
// bf16 K/Q projection: KQ[z] = bf16(Xb @ Wb[z]^T + bias_z), z=0(K),1(Q)
// ---------------------------------------------------------------------------
__global__ __launch_bounds__(256) void gemm_kq_bf16(
    const float* __restrict__ bk_, const float* __restrict__ bq_)
{
    extern __shared__ char smem[];
    const uint32_t sbase = smem_u32(smem);
    float* sOut = (float*)smem;
    const int tid = threadIdx.x;
    const int lane = tid & 31, wid = tid >> 5;
    const int m0 = blockIdx.y * 128, n0 = blockIdx.x * 128;
    const int z = blockIdx.z;

    const char* Ab = (const char*)g_Xb;
    const char* Bb = (const char*)(g_Wb + (size_t)z * DD * DD);
    const float* bias = z ? bq_ : bk_;

    FragAddr F = make_addr(tid);
    uint32_t gA[4], gB[4];
#pragma unroll
    for (int i = 0; i < 4; i++) {
        int g = tid + 256 * i;
        int row = g >> 3, cb = (g & 7) * 16;
        gA[i] = (uint32_t)((m0 + row) * DD) * 2u + (uint32_t)cb;
        gB[i] = (uint32_t)((n0 + row) * DD) * 2u + (uint32_t)cb;
    }

    float acc[4][4][4];
#pragma unroll
    for (int f = 0; f < 4; f++)
#pragma unroll
        for (int nf = 0; nf < 4; nf++)
#pragma unroll
            for (int r = 0; r < 4; r++) acc[f][nf][r] = 0.f;

    auto load_chunk = [&](int c, int s) {
        uint32_t stA = sbase + (uint32_t)s * STAGE_BYTES;
        uint32_t stB = stA + STAGE_A;
        uint32_t ko = (uint32_t)c * 128u;
#pragma unroll
        for (int i = 0; i < 4; i++) {
            CP_ASYNC16(stA + F.so[i], Ab + gA[i] + ko);
            CP_ASYNC16(stB + F.so[i], Bb + gB[i] + ko);
        }
    };

    load_chunk(0, 0); CP_COMMIT();
    load_chunk(1, 1); CP_COMMIT();
    for (int c = 0; c < NCH_BF16; c++) {
        CP_WAIT(1);
        __syncthreads();
        if (c + 2 < NCH_BF16) load_chunk(c + 2, (c + 2) % 3);
        CP_COMMIT();
        uint32_t stA = sbase + (uint32_t)(c % 3) * STAGE_BYTES;
        compute_stage<1>(F, stA, stA + STAGE_A, acc);
    }
    __syncthreads();
    acc_to_smem(sOut, lane, wid, acc);
    __syncthreads();

    const int col = (tid & 31) * 4;
    float4 bv = *(const float4*)&bias[n0 + col];
    __nv_bfloat16* Cb = g_KQ + (size_t)z * MT * DD;
#pragma unroll
    for (int i = 0; i < 16; i++) {
        int row = (tid >> 5) + i * 8;
        float4 v = *(float4*)&sOut[row * SOUT_STRIDE + col];
        v.x += bv.x; v.y += bv.y; v.z += bv.z; v.w += bv.w;
        __nv_bfloat162 p0 = __floats2bfloat162_rn(v.x, v.y);
        __nv_bfloat162 p1 = __floats2bfloat162_rn(v.z, v.w);
        uint2 pk = make_uint2(*(uint32_t*)&p0, *(uint32_t*)&p1);
        *(uint2*)&Cb[(size_t)(m0 + row) * DD + n0 + col] = pk;
    }
}

// ---------------------------------------------------------------------------
// bf16 qk GEMM: E[b] = bf16(exp((K_b @ Q_b^T)/512)), column sums into g_Z.
// ---------------------------------------------------------------------------
__global__ __launch_bounds__(256) void gemm_qk_bf16()
{
    extern __shared__ char smem[];
    const uint32_t sbase = smem_u32(smem);
    float* sOut = (float*)smem;
    float* sZ   = (float*)(smem + SMEM_MAIN);
    const int tid = threadIdx.x;
    const int lane = tid & 31, wid = tid >> 5;
    const int m0 = blockIdx.y * 128, n0 = blockIdx.x * 128;
    const int z = blockIdx.z;

    const char* Ab = (const char*)(g_KQ + (size_t)z * SS * DD);
    const char* Bb = (const char*)(g_KQ + (size_t)MT * DD + (size_t)z * SS * DD);

    if (tid < 128) sZ[tid] = 0.f;

    FragAddr F = make_addr(tid);
    uint32_t gA[4], gB[4];
#pragma unroll
    for (int i = 0; i < 4; i++) {
        int g = tid + 256 * i;
        int row = g >> 3, cb = (g & 7) * 16;
        gA[i] = (uint32_t)((m0 + row) * DD) * 2u + (uint32_t)cb;
        gB[i] = (uint32_t)((n0 + row) * DD) * 2u + (uint32_t)cb;
    }

    float acc[4][4][4];
#pragma unroll
    for (int f = 0; f < 4; f++)
#pragma unroll
        for (int nf = 0; nf < 4; nf++)
#pragma unroll
            for (int r = 0; r < 4; r++) acc[f][nf][r] = 0.f;

    auto load_chunk = [&](int c, int s) {
        uint32_t stA = sbase + (uint32_t)s * STAGE_BYTES;
        uint32_t stB = stA + STAGE_A;
        uint32_t ko = (uint32_t)c * 128u;
#pragma unroll
        for (int i = 0; i < 4; i++) {
            CP_ASYNC16(stA + F.so[i], Ab + gA[i] + ko);
            CP_ASYNC16(stB + F.so[i], Bb + gB[i] + ko);
        }
    };

    load_chunk(0, 0); CP_COMMIT();
    load_chunk(1, 1); CP_COMMIT();
    for (int c = 0; c < NCH_BF16; c++) {
        CP_WAIT(1);
        __syncthreads();
        if (c + 2 < NCH_BF16) load_chunk(c + 2, (c + 2) % 3);
        CP_COMMIT();
        uint32_t stA = sbase + (uint32_t)(c % 3) * STAGE_BYTES;
        compute_stage<1>(F, stA, stA + STAGE_A, acc);
    }
    __syncthreads();
    acc_to_smem(sOut, lane, wid, acc);
    __syncthreads();

    const int col = (tid & 31) * 4;
    float csum0 = 0.f, csum1 = 0.f, csum2 = 0.f, csum3 = 0.f;
    const float inv512 = 0.001953125f;
    __nv_bfloat16* Cb = g_E + (size_t)z * SS * SS;
#pragma unroll
    for (int i = 0; i < 16; i++) {
        int row = (tid >> 5) + i * 8;
        float4 v = *(float4*)&sOut[row * SOUT_STRIDE + col];
        v.x = __expf(v.x * inv512); v.y = __expf(v.y * inv512);
        v.z = __expf(v.z * inv512); v.w = __expf(v.w * inv512);
        csum0 += v.x; csum1 += v.y; csum2 += v.z; csum3 += v.w;
        __nv_bfloat162 p0 = __floats2bfloat162_rn(v.x, v.y);
        __nv_bfloat162 p1 = __floats2bfloat162_rn(v.z, v.w);
        uint2 pk = make_uint2(*(uint32_t*)&p0, *(uint32_t*)&p1);
        *(uint2*)&Cb[(size_t)(m0 + row) * SS + n0 + col] = pk;
    }
    atomicAdd(&sZ[col + 0], csum0);
    atomicAdd(&sZ[col + 1], csum1);
    atomicAdd(&sZ[col + 2], csum2);
    atomicAdd(&sZ[col + 3], csum3);
    __syncthreads();
    if (tid < 128)
        atomicAdd(&g_Z[(size_t)z * SS + n0 + tid], sZ[tid]);
}

// ---------------------------------------------------------------------------
// Prep kernels (right-sized grids; no near-empty blocks)
// ---------------------------------------------------------------------------
// xs -> g_X (tf32-rna) and g_Xb (bf16)
__global__ __launch_bounds__(256) void prepX_kernel(const float* __restrict__ xs)
{
    const int t = blockIdx.x * 256 + threadIdx.x;
    float4 v = ((const float4*)xs)[t];
    float4 r;
    r.x = round_tf32(v.x); r.y = round_tf32(v.y);
    r.z = round_tf32(v.z); r.w = round_tf32(v.w);
    ((float4*)g_X)[t] = r;
    __nv_bfloat162 p0 = __floats2bfloat162_rn(v.x, v.y);
    __nv_bfloat162 p1 = __floats2bfloat162_rn(v.z, v.w);
    ((uint2*)g_Xb)[t] = make_uint2(*(uint32_t*)&p0, *(uint32_t*)&p1);
}

// y=0: Wk->g_Wb[0] bf16; y=1: Wq->g_Wb[1] bf16; y=2: Wv->g_Wv tf32; y=3: Wl->g_Wl tf32
__global__ __launch_bounds__(256) void prepW_kernel(
    const float* __restrict__ Wk, const float* __restrict__ Wq,
    const float* __restrict__ Wv, const float* __restrict__ Wl)
{
    const int t = blockIdx.x * 256 + threadIdx.x;
    const int which = blockIdx.y;
    if (which < 2) {
        float4 v = ((const float4*)(which ? Wq : Wk))[t];
        __nv_bfloat162 p0 = __floats2bfloat162_rn(v.x, v.y);
        __nv_bfloat162 p1 = __floats2bfloat162_rn(v.z, v.w);
        ((uint2*)(g_Wb + (size_t)which * DD * DD))[t] =
            make_uint2(*(uint32_t*)&p0, *(uint32_t*)&p1);
    } else {
        float4 v = ((const float4*)(which == 2 ? Wv : Wl))[t];
        v.x = round_tf32(v.x); v.y = round_tf32(v.y);
        v.z = round_tf32(v.z); v.w = round_tf32(v.w);
        ((float4*)(which == 2 ? g_Wv : g_Wl))[t] = v;
    }
}

__global__ void zeroZ_kernel() {
    int i = blockIdx.x * 256 + threadIdx.x;
    if (i < MT) g_Z[i] = 0.f;
}
__global__ void invZ_kernel() {
    int i = blockIdx.x * 256 + threadIdx.x;
    if (i < MT) g_Z[i] = 1.0f / g_Z[i];
}

// rowsum[m] = sum_e E[m,e]*invZ[b,e] (E bf16), then scale V row in place.
__global__ __launch_bounds__(256) void rowsum_scale_kernel()
{
    const int m = blockIdx.x;
    const int b = m >> 12;
    const __nv_bfloat16* __restrict__ Er = g_E + (size_t)m * SS;
    const float* __restrict__ iz = g_Z + b * SS;
    float s = 0.f;
#pragma unroll
    for (int it = 0; it < 2; it++) {
        int e = (threadIdx.x + it * 256) * 8;
        uint4 raw = *(const uint4*)(Er + e);
        float4 z0 = *(const float4*)(iz + e);
        float4 z1 = *(const float4*)(iz + e + 4);
        float2 p0 = __bfloat1622float2(*(__nv_bfloat162*)&raw.x);
        float2 p1 = __bfloat1622float2(*(__nv_bfloat162*)&raw.y);
        float2 p2 = __bfloat1622float2(*(__nv_bfloat162*)&raw.z);
        float2 p3 = __bfloat1622float2(*(__nv_bfloat162*)&raw.w);
        s += p0.x * z0.x + p0.y * z0.y + p1.x * z0.z + p1.y * z0.w
           + p2.x * z1.x + p2.y * z1.y + p3.x * z1.z + p3.y * z1.w;
    }
#pragma unroll
    for (int o = 16; o > 0; o >>= 1) s += __shfl_xor_sync(0xffffffffu, s, o);
    __shared__ float red[8];
    __shared__ float rbc;
    if ((threadIdx.x & 31) == 0) red[threadIdx.x >> 5] = s;
    __syncthreads();
    if (threadIdx.x == 0) {
        float t = 0.f;
#pragma unroll
        for (int w = 0; w < 8; w++) t += red[w];
        g_rowsum[m] = t;
        rbc = t;
    }
    __syncthreads();
    const float r = rbc;
    float4* v = (float4*)(g_V + (size_t)m * DD);
    if (threadIdx.x < 128) {
        float4 x = v[threadIdx.x];
        x.x = round_tf32(x.x * r); x.y = round_tf32(x.y * r);
        x.z = round_tf32(x.z * r); x.w = round_tf32(x.w * r);
        v[threadIdx.x] = x;
    }
}

// ---------------------------------------------------------------------------
extern "C" void kernel_launch(void* const* d_in, const int* in_sizes, int n_in,
                              void* d_out, int out_size)
{
    const float* xs = (const float*)d_in[0];
    const float* Wk = (const float*)d_in[1];
    const float* bk = (const float*)d_in[2];
    const float* Wq = (const float*)d_in[3];
    const float* bq = (const float*)d_in[4];
    const float* Wv = (const float*)d_in[5];
    const float* bv = (const float*)d_in[6];
    const float* Wl = (const float*)d_in[7];
    const float* bl = (const float*)d_in[8];
    float* out = (float*)d_out;
    (void)in_sizes; (void)n_in; (void)out_size;

    float *pX, *pWv, *pWl, *pV;
    cudaGetSymbolAddress((void**)&pX, g_X);
    cudaGetSymbolAddress((void**)&pWv, g_Wv);
    cudaGetSymbolAddress((void**)&pWl, g_Wl);
    cudaGetSymbolAddress((void**)&pV, g_V);

    cudaFuncSetAttribute(gemm_tf32<0>, cudaFuncAttributeMaxDynamicSharedMemorySize, SMEM_TOTAL);
    cudaFuncSetAttribute(gemm_tf32<2>, cudaFuncAttributeMaxDynamicSharedMemorySize, SMEM_TOTAL);
    cudaFuncSetAttribute(gemm_kq_bf16, cudaFuncAttributeMaxDynamicSharedMemorySize, SMEM_TOTAL);
    cudaFuncSetAttribute(gemm_qk_bf16, cudaFuncAttributeMaxDynamicSharedMemorySize, SMEM_TOTAL);

    zeroZ_kernel<<<MT / 256, 256>>>();
    prepX_kernel<<<MT * DD / 1024, 256>>>(xs);
    prepW_kernel<<<dim3(DD * DD / 1024, 4), 256>>>(Wk, Wq, Wv, Wl);
    // K/Q projections in bf16 (2x MMA rate)
    gemm_kq_bf16<<<dim3(4, 128, 2), 256, SMEM_TOTAL>>>(bk, bq);
    // V projection in tf32 (precision-critical path)
    gemm_tf32<0><<<dim3(4, 128), 256, SMEM_TOTAL>>>(pX, pWv, bv, pV);
    // qk in bf16
    gemm_qk_bf16<<<dim3(32, 32, BB), 256, SMEM_TOTAL>>>();
    invZ_kernel<<<MT / 256, 256>>>();
    rowsum_scale_kernel<<<MT, 256>>>();
    // out = tanh((rowsum.*V) @ Wl^T + bl)
    gemm_tf32<2><<<dim3(4, 128), 256, SMEM_TOTAL>>>(pV, pWl, bl, out);
}